// round 5
// baseline (speedup 1.0000x reference)
#include <cuda_runtime.h>
#include <math.h>

#define Bn 4
#define Sn 2048
#define En 1024
#define Hn 16
#define Dn 64
#define Mn (Bn*Sn)          // 8192

// ---------------------------------------------------------------------------
// Scratch buffers (device globals; allocation is forbidden)
// ---------------------------------------------------------------------------
__device__ __align__(16) float g_q[(size_t)Mn*En];     // [H][S][B][D]
__device__ __align__(16) float g_k[(size_t)Mn*En];     // [H][S][B][D]
__device__ __align__(16) float g_v[(size_t)Mn*En];     // [H][S][B][D]
__device__ __align__(16) float g_gate[(size_t)Mn*En];  // [B*S][E]
__device__ __align__(16) float g_o1[(size_t)Mn*En];    // [B*S][E]

// ---------------------------------------------------------------------------
// Packed-f32 helpers
// ---------------------------------------------------------------------------
typedef unsigned long long ull;

__device__ __forceinline__ ull ffma2(ull a, ull b, ull c) {
    ull d;
    asm("fma.rn.f32x2 %0, %1, %2, %3;" : "=l"(d) : "l"(a), "l"(b), "l"(c));
    return d;
}
__device__ __forceinline__ ull pack2(float x, float y) {
    ull r;
    asm("mov.b64 %0, {%1, %2};" : "=l"(r) : "f"(x), "f"(y));
    return r;
}
__device__ __forceinline__ float2 unpack2(ull u) {
    float2 f;
    asm("mov.b64 {%0, %1}, %2;" : "=f"(f.x), "=f"(f.y) : "l"(u));
    return f;
}

// Warp-local N-value xor-tree reduction over 32 lanes (batched per round).
template<int N>
__device__ __forceinline__ void wredN(float* v)
{
#pragma unroll
    for (int off = 16; off > 0; off >>= 1)
#pragma unroll
        for (int i = 0; i < N; i++)
            v[i] += __shfl_xor_sync(0xffffffffu, v[i], off);
}

// ---------------------------------------------------------------------------
// NT GEMM body with f32x2 packed FMA. C[m][n] = sum_k A[m][k]*Bw[n][k].
// 128x128 tile, 256 thr, 8 rows x 4 col-pairs per thread, BK=8, dbl buffered.
// MODE 0: scatter to [H][S][B][D];  MODE 1: flat.
// ---------------------------------------------------------------------------
template<int MODE>
__device__ __forceinline__ void gemm_body(const float* __restrict__ A,
                                          const float* __restrict__ Bw,
                                          float* __restrict__ C,
                                          int bm, int bn)
{
    __shared__ __align__(16) float As[2][8][132];
    __shared__ __align__(16) float Bs[2][8][132];

    const int t = threadIdx.x;
    const int arow = t >> 1;
    const int ak   = (t & 1) * 4;
    const int tx = t & 15;
    const int ty = t >> 4;

    const float* Ag = A  + (size_t)(bm*128 + arow)*1024 + ak;
    const float* Bg = Bw + (size_t)(bn*128 + arow)*1024 + ak;

    ull acc2[8][4];
#pragma unroll
    for (int i = 0; i < 8; i++)
#pragma unroll
        for (int j = 0; j < 4; j++) acc2[i][j] = 0ULL;

    {
        float4 av = *(const float4*)Ag;
        float4 bv = *(const float4*)Bg;
        As[0][ak+0][arow] = av.x; As[0][ak+1][arow] = av.y;
        As[0][ak+2][arow] = av.z; As[0][ak+3][arow] = av.w;
        Bs[0][ak+0][arow] = bv.x; Bs[0][ak+1][arow] = bv.y;
        Bs[0][ak+2][arow] = bv.z; Bs[0][ak+3][arow] = bv.w;
    }
    __syncthreads();

#pragma unroll 1
    for (int kt = 0; kt < 128; kt++) {
        const int buf = kt & 1;
        float4 av2, bv2;
        const bool more = (kt + 1 < 128);
        if (more) {
            av2 = *(const float4*)(Ag + (kt+1)*8);
            bv2 = *(const float4*)(Bg + (kt+1)*8);
        }
#pragma unroll
        for (int kk = 0; kk < 8; kk++) {
            float a[8];
            *(float4*)&a[0]  = *(const float4*)&As[buf][kk][ty*4];
            *(float4*)&a[4]  = *(const float4*)&As[buf][kk][64 + ty*4];
            ulonglong2 b0 = *(const ulonglong2*)&Bs[buf][kk][tx*4];
            ulonglong2 b1 = *(const ulonglong2*)&Bs[buf][kk][64 + tx*4];
#pragma unroll
            for (int i = 0; i < 8; i++) {
                ull as = pack2(a[i], a[i]);
                acc2[i][0] = ffma2(as, b0.x, acc2[i][0]);
                acc2[i][1] = ffma2(as, b0.y, acc2[i][1]);
                acc2[i][2] = ffma2(as, b1.x, acc2[i][2]);
                acc2[i][3] = ffma2(as, b1.y, acc2[i][3]);
            }
        }
        if (more) {
            const int nb = buf ^ 1;
            As[nb][ak+0][arow] = av2.x; As[nb][ak+1][arow] = av2.y;
            As[nb][ak+2][arow] = av2.z; As[nb][ak+3][arow] = av2.w;
            Bs[nb][ak+0][arow] = bv2.x; Bs[nb][ak+1][arow] = bv2.y;
            Bs[nb][ak+2][arow] = bv2.z; Bs[nb][ak+3][arow] = bv2.w;
            __syncthreads();
        }
    }

#pragma unroll
    for (int i = 0; i < 8; i++) {
        const int r = (i < 4) ? (ty*4 + i) : (64 + ty*4 + (i - 4));
        const int m = bm*128 + r;
        float2 c0 = unpack2(acc2[i][0]);
        float2 c1 = unpack2(acc2[i][1]);
        float2 c2 = unpack2(acc2[i][2]);
        float2 c3 = unpack2(acc2[i][3]);
        float4 v0 = make_float4(c0.x, c0.y, c1.x, c1.y);
        float4 v1 = make_float4(c2.x, c2.y, c3.x, c3.y);
#pragma unroll
        for (int jg = 0; jg < 2; jg++) {
            const int c = bn*128 + (jg ? (64 + tx*4) : (tx*4));
            float4 vv = jg ? v1 : v0;
            if (MODE == 0) {
                const int bb_ = m >> 11;
                const int sI  = m & 2047;
                const int hh  = c >> 6;
                const int d   = c & 63;
                *(float4*)&C[(((size_t)hh*Sn + sI)*Bn + bb_)*Dn + d] = vv;
            } else {
                *(float4*)&C[(size_t)m*En + c] = vv;
            }
        }
    }
}

template<int MODE>
__global__ void __launch_bounds__(256, 2) gemm_nt(const float* __restrict__ A,
                                                  const float* __restrict__ Bw,
                                                  float* __restrict__ C)
{
    gemm_body<MODE>(A, Bw, C, blockIdx.y, blockIdx.x);
}

// ---------------------------------------------------------------------------
// TTT scan body: one CTA per head, 256 threads = 8 warps.
// Warp w owns W rows [8w, 8w+8). Warps 0..3 additionally run the per-token
// math for batch b = w (one math warp per SMSP); lane owns e = {2l, 2l+1}.
// Reductions: batched shfl_xor butterflies. 3 __syncthreads per token.
// k stored pre-splatted in smem so forward/update use fma.rn.f32x2.
// ---------------------------------------------------------------------------
__device__ __forceinline__ void scan_body(
    const float* __restrict__ fw_W, const float* __restrict__ fw_b,
    const float* __restrict__ fw_g, const float* __restrict__ fw_bl,
    const float* __restrict__ ttt_g, const float* __restrict__ ttt_b)
{
    const int h = blockIdx.x;
    const int t = threadIdx.x;
    const int w = t >> 5;
    const int l = t & 31;
    const int e0 = 2*l;
    const bool mathw = (w < 4);
    const int b = w & 3;
    const int dbase = w * 8;

    __shared__ __align__(16) float2 k2_s[4][4][64];     // [buf][b][d] splatted
    __shared__ __align__(16) ull    part_s[4][8][32];   // [b'][w][l]
    __shared__ __align__(16) float2 ex_dh[4][32],  ex_dp[4][32],  ex_dph[4][32];
    __shared__ __align__(16) float2 ex2_dh[4][32], ex2_dp[4][32], ex2_dph[4][32];
    __shared__ __align__(16) float2 dhs_s[4][32];

    // W slice (packed e-pairs)
    ull Wr2[8];
    {
        const float* W0 = fw_W + ((size_t)h*Dn + dbase)*Dn + e0;
#pragma unroll
        for (int i = 0; i < 8; i++) Wr2[i] = pack2(W0[i*Dn], W0[i*Dn + 1]);
    }

    const float LR = 0.1f, EPS = 1e-5f;
    const float C0 = 2.0f/4096.0f, IN = 1.0f/64.0f;

    float bp0=0,bp1=0,gp0=0,gp1=0,blp0=0,blp1=0,tg0=0,tg1=0,tb0=0,tb1=0;
    const float *kh=0,*vh=0,*qh=0;
    float2 kc=make_float2(0,0), vc=kc, qc=kc, kn=kc, vn=kc, qn=kc;

    if (mathw) {
        bp0  = fw_b [h*Dn + e0]; bp1  = fw_b [h*Dn + e0 + 1];
        gp0  = fw_g [h*Dn + e0]; gp1  = fw_g [h*Dn + e0 + 1];
        blp0 = fw_bl[h*Dn + e0]; blp1 = fw_bl[h*Dn + e0 + 1];
        tg0  = ttt_g[h*Dn + e0]; tg1  = ttt_g[h*Dn + e0 + 1];
        tb0  = ttt_b[h*Dn + e0]; tb1  = ttt_b[h*Dn + e0 + 1];
        kh = g_k + (size_t)h*Sn*256 + b*64 + e0;
        vh = g_v + (size_t)h*Sn*256 + b*64 + e0;
        qh = g_q + (size_t)h*Sn*256 + b*64 + e0;
        kc = *(const float2*)kh;  vc = *(const float2*)vh;  qc = *(const float2*)qh;
        kn = *(const float2*)(kh + 256);
        vn = *(const float2*)(vh + 256);
        qn = *(const float2*)(qh + 256);
        *(float4*)&k2_s[0][b][e0] = make_float4(kc.x, kc.x, kc.y, kc.y);
    }
    __syncthreads();

    for (int s = 0; s < Sn; s++) {
        const int buf = s & 3;

        // ---- forward partials: all 8 warps, packed FMA over 8 W rows
#pragma unroll
        for (int bb = 0; bb < 4; bb++) {
            const ulonglong2* kp4 = (const ulonglong2*)&k2_s[buf][bb][dbase];
            ull acc = 0ULL;
#pragma unroll
            for (int i = 0; i < 4; i++) {
                ulonglong2 kk = kp4[i];
                acc = ffma2(kk.x, Wr2[2*i],   acc);
                acc = ffma2(kk.y, Wr2[2*i+1], acc);
            }
            part_s[bb][w][l] = acc;
        }

        float rr[6] = {0,0,0,0,0,0};
        if (mathw) {
            float4 t0 = *(const float4*)&k2_s[buf][0][e0];
            float4 t1 = *(const float4*)&k2_s[buf][1][e0];
            float4 t2 = *(const float4*)&k2_s[buf][2][e0];
            float4 t3 = *(const float4*)&k2_s[buf][3][e0];
            rr[2] = kc.x*t0.x + kc.y*t0.z;
            rr[3] = kc.x*t1.x + kc.y*t1.z;
            rr[4] = kc.x*t2.x + kc.y*t2.z;
            rr[5] = kc.x*t3.x + kc.y*t3.z;
            if (s + 1 < Sn)
                *(float4*)&k2_s[(s+1)&3][b][e0] = make_float4(kn.x, kn.x, kn.y, kn.y);
        }
        __syncthreads();                                  // S3

        float h00=0,h01=0, hat00=0,hat01=0, dh00=0,dh01=0;
        float G0=0,G1=0,G2=0,G3=0, tgt0=0,tgt1=0;
        if (mathw) {
            h00 = bp0; h01 = bp1;
#pragma unroll
            for (int g = 0; g < 8; g++) {
                float2 pv = unpack2(part_s[b][g][l]);
                h00 += pv.x; h01 += pv.y;
            }
            rr[0] = h00 + h01;
            rr[1] = h00*h00 + h01*h01;
            wredN<6>(rr);
            G0 = rr[2]; G1 = rr[3]; G2 = rr[4]; G3 = rr[5];
            const float mu0 = rr[0]*IN;
            const float rs0 = rsqrtf(rr[1]*IN - mu0*mu0 + EPS);
            hat00 = (h00 - mu0)*rs0;  hat01 = (h01 - mu0)*rs0;
            tgt0 = vc.x - kc.x;       tgt1 = vc.y - kc.y;
            const float dp00 = C0*(hat00*gp0 + blp0 - tgt0);
            const float dp01 = C0*(hat01*gp1 + blp1 - tgt1);
            const float dhat00 = dp00*gp0, dhat01 = dp01*gp1;
            float r2[2] = { dhat00 + dhat01, dhat00*hat00 + dhat01*hat01 };
            wredN<2>(r2);
            dh00 = rs0*(dhat00 - r2[0]*IN - hat00*(r2[1]*IN));
            dh01 = rs0*(dhat01 - r2[0]*IN - hat01*(r2[1]*IN));
            ex_dh [b][l] = make_float2(dh00, dh01);
            ex_dp [b][l] = make_float2(dp00, dp01);
            ex_dph[b][l] = make_float2(dp00*hat00, dp01*hat01);
        }
        __syncthreads();                                  // S4

        float g10=0,g11=0, bl10=0,bl11=0, b10=0,b11=0, h10=0,h11=0;
        if (mathw) {
            float2 a0 = ex_dh[0][l], a1 = ex_dh[1][l], a2 = ex_dh[2][l], a3 = ex_dh[3][l];
            float2 p0 = ex_dp[0][l], p1 = ex_dp[1][l], p2 = ex_dp[2][l], p3 = ex_dp[3][l];
            float2 c0 = ex_dph[0][l],c1 = ex_dph[1][l],c2 = ex_dph[2][l],c3 = ex_dph[3][l];
            const float sdh0 = a0.x+a1.x+a2.x+a3.x, sdh1 = a0.y+a1.y+a2.y+a3.y;
            const float gd0  = G0*a0.x+G1*a1.x+G2*a2.x+G3*a3.x;
            const float gd1  = G0*a0.y+G1*a1.y+G2*a2.y+G3*a3.y;
            const float sdp0 = p0.x+p1.x+p2.x+p3.x, sdp1 = p0.y+p1.y+p2.y+p3.y;
            const float sq0  = c0.x+c1.x+c2.x+c3.x, sq1  = c0.y+c1.y+c2.y+c3.y;
            g10 = gp0 - LR*sq0;   g11 = gp1 - LR*sq1;
            bl10 = blp0 - LR*sdp0; bl11 = blp1 - LR*sdp1;
            b10 = bp0 - LR*sdh0;  b11 = bp1 - LR*sdh1;
            h10 = h00 - LR*(gd0 + sdh0);
            h11 = h01 - LR*(gd1 + sdh1);

            float r3[2] = { h10 + h11, h10*h10 + h11*h11 };
            wredN<2>(r3);
            const float mu1 = r3[0]*IN;
            const float rs1 = rsqrtf(r3[1]*IN - mu1*mu1 + EPS);
            const float hat10 = (h10 - mu1)*rs1, hat11 = (h11 - mu1)*rs1;
            const float dp10 = C0*(hat10*g10 + bl10 - tgt0);
            const float dp11 = C0*(hat11*g11 + bl11 - tgt1);
            const float dhat10 = dp10*g10, dhat11 = dp11*g11;
            float r4[2] = { dhat10 + dhat11, dhat10*hat10 + dhat11*hat11 };
            wredN<2>(r4);
            const float dh10 = rs1*(dhat10 - r4[0]*IN - hat10*(r4[1]*IN));
            const float dh11 = rs1*(dhat11 - r4[0]*IN - hat11*(r4[1]*IN));
            ex2_dh [b][l] = make_float2(dh10, dh11);
            ex2_dp [b][l] = make_float2(dp10, dp11);
            ex2_dph[b][l] = make_float2(dp10*hat10, dp11*hat11);
            dhs_s  [b][l] = make_float2(dh00 + dh10, dh01 + dh11);
        }
        __syncthreads();                                  // S5

        if (mathw) {
            float2 a0 = ex2_dh[0][l], a1 = ex2_dh[1][l], a2 = ex2_dh[2][l], a3 = ex2_dh[3][l];
            float2 p0 = ex2_dp[0][l], p1 = ex2_dp[1][l], p2 = ex2_dp[2][l], p3 = ex2_dp[3][l];
            float2 c0 = ex2_dph[0][l],c1 = ex2_dph[1][l],c2 = ex2_dph[2][l],c3 = ex2_dph[3][l];
            const float sdh0 = a0.x+a1.x+a2.x+a3.x, sdh1 = a0.y+a1.y+a2.y+a3.y;
            const float gd0  = G0*a0.x+G1*a1.x+G2*a2.x+G3*a3.x;
            const float gd1  = G0*a0.y+G1*a1.y+G2*a2.y+G3*a3.y;
            const float sdp0 = p0.x+p1.x+p2.x+p3.x, sdp1 = p0.y+p1.y+p2.y+p3.y;
            const float sq0  = c0.x+c1.x+c2.x+c3.x, sq1  = c0.y+c1.y+c2.y+c3.y;
            const float g20 = g10 - LR*sq0,  g21 = g11 - LR*sq1;
            const float bl20 = bl10 - LR*sdp0, bl21 = bl11 - LR*sdp1;
            bp0 = b10 - LR*sdh0;  bp1 = b11 - LR*sdh1;
            const float h20 = h10 - LR*(gd0 + sdh0);
            const float h21 = h11 - LR*(gd1 + sdh1);

            float r5[2] = { h20 + h21, h20*h20 + h21*h21 };
            wredN<2>(r5);
            const float mu2 = r5[0]*IN;
            const float rs2 = rsqrtf(r5[1]*IN - mu2*mu2 + EPS);
            const float z0 = (h20 - mu2)*rs2*g20 + bl20;
            const float z1 = (h21 - mu2)*rs2*g21 + bl21;
            float r6[2] = { z0 + z1, z0*z0 + z1*z1 };
            wredN<2>(r6);
            const float muz = r6[0]*IN;
            const float rsz = rsqrtf(r6[1]*IN - muz*muz + EPS);
            float2 o;
            o.x = qc.x + (z0 - muz)*rsz*tg0 + tb0;
            o.y = qc.y + (z1 - muz)*rsz*tg1 + tb1;
            *(float2*)&g_o1[((size_t)(b*Sn + s))*En + h*Dn + e0] = o;

            gp0 = g20; gp1 = g21; blp0 = bl20; blp1 = bl21;

            // rotate + prefetch
            kc = kn; vc = vn; qc = qn;
            const int nidx = (s + 2 < Sn) ? (s + 2) : (Sn - 1);
            kn = *(const float2*)(kh + (size_t)nidx*256);
            vn = *(const float2*)(vh + (size_t)nidx*256);
            qn = *(const float2*)(qh + (size_t)nidx*256);
        }

        // ---- W update: all warps, packed FMA
        ull cb[4];
#pragma unroll
        for (int bb = 0; bb < 4; bb++) {
            float2 dv = dhs_s[bb][l];
            cb[bb] = pack2(-LR*dv.x, -LR*dv.y);
        }
#pragma unroll
        for (int bb = 0; bb < 4; bb++) {
            const ulonglong2* kp4 = (const ulonglong2*)&k2_s[buf][bb][dbase];
#pragma unroll
            for (int i = 0; i < 4; i++) {
                ulonglong2 kk = kp4[i];
                Wr2[2*i]   = ffma2(kk.x, cb[bb], Wr2[2*i]);
                Wr2[2*i+1] = ffma2(kk.y, cb[bb], Wr2[2*i+1]);
            }
        }
    }
}

// ---------------------------------------------------------------------------
// Fat kernel: blocks 0..15 scan (one SM each, occupancy 1 so no GEMM CTA
// co-resides); blocks 16..527 run the gate GEMM on the idle SMs.
// ---------------------------------------------------------------------------
__global__ void __launch_bounds__(256, 1) scan_plus_gate(
    const float* __restrict__ x, const float* __restrict__ Wg,
    const float* __restrict__ fw_W, const float* __restrict__ fw_b,
    const float* __restrict__ fw_g, const float* __restrict__ fw_bl,
    const float* __restrict__ ttt_g, const float* __restrict__ ttt_b)
{
    if (blockIdx.x >= 16) {
        const int bid = blockIdx.x - 16;
        gemm_body<1>(x, Wg, g_gate, bid >> 3, bid & 7);
        return;
    }
    scan_body(fw_W, fw_b, fw_g, fw_bl, ttt_g, ttt_b);
}

// ---------------------------------------------------------------------------
// Fused post-LayerNorm * gelu(gate), in-place into g_gate.
// ---------------------------------------------------------------------------
__global__ void __launch_bounds__(256, 1) postgate_kernel(
    const float* __restrict__ pg, const float* __restrict__ pb)
{
    const int row = blockIdx.x;
    const int t = threadIdx.x;
    const int w = t >> 5, lane = t & 31;
    const float* xr = g_o1 + (size_t)row*En;

    float v[4];
    float s = 0.f, ss = 0.f;
#pragma unroll
    for (int j = 0; j < 4; j++) {
        float xv = xr[t + 256*j];
        v[j] = xv; s += xv; ss += xv*xv;
    }
#pragma unroll
    for (int off = 16; off > 0; off >>= 1) {
        s  += __shfl_xor_sync(0xffffffffu, s, off);
        ss += __shfl_xor_sync(0xffffffffu, ss, off);
    }
    __shared__ float rsm[16];
    if (lane == 0) { rsm[w] = s; rsm[8 + w] = ss; }
    __syncthreads();
    float S = 0.f, SS = 0.f;
#pragma unroll
    for (int i = 0; i < 8; i++) { S += rsm[i]; SS += rsm[8 + i]; }
    const float mu = S * (1.0f/1024.0f);
    const float r  = rsqrtf(SS * (1.0f/1024.0f) - mu*mu + 1e-5f);

    float* gr = g_gate + (size_t)row*En;
#pragma unroll
    for (int j = 0; j < 4; j++) {
        const int e_ = t + 256*j;
        const float y  = (v[j] - mu)*r*pg[e_] + pb[e_];
        const float xg = gr[e_];
        const float gl = 0.5f*xg*(1.0f + tanhf(0.7978845608028654f*
                                 (xg + 0.044715f*xg*xg*xg)));
        gr[e_] = y * gl;
    }
}

// ---------------------------------------------------------------------------
extern "C" void kernel_launch(void* const* d_in, const int* in_sizes, int n_in,
                              void* d_out, int out_size)
{
    const float* x    = (const float*)d_in[0];
    const float* Wq   = (const float*)d_in[1];
    const float* Wk   = (const float*)d_in[2];
    const float* Wv   = (const float*)d_in[3];
    const float* Wo   = (const float*)d_in[4];
    const float* Wg   = (const float*)d_in[5];
    const float* fwW  = (const float*)d_in[6];
    const float* fwb  = (const float*)d_in[7];
    const float* fwg  = (const float*)d_in[8];
    const float* fwbl = (const float*)d_in[9];
    const float* tttg = (const float*)d_in[10];
    const float* tttb = (const float*)d_in[11];
    const float* pg   = (const float*)d_in[12];
    const float* pb   = (const float*)d_in[13];
    float* out = (float*)d_out;

    float *pq, *pk, *pv, *pgt;
    cudaGetSymbolAddress((void**)&pq,  g_q);
    cudaGetSymbolAddress((void**)&pk,  g_k);
    cudaGetSymbolAddress((void**)&pv,  g_v);
    cudaGetSymbolAddress((void**)&pgt, g_gate);

    dim3 grid(En/128, Mn/128), blk(256);
    gemm_nt<0><<<grid, blk>>>(x, Wq, pq);
    gemm_nt<0><<<grid, blk>>>(x, Wk, pk);
    gemm_nt<0><<<grid, blk>>>(x, Wv, pv);
    scan_plus_gate<<<16 + 512, 256>>>(x, Wg, fwW, fwb, fwg, fwbl, tttg, tttb);
    postgate_kernel<<<Mn, 256>>>(pg, pb);
    gemm_nt<1><<<grid, blk>>>(pgt, Wo, out);
}